// round 5
// baseline (speedup 1.0000x reference)
#include <cuda_runtime.h>
#include <cstdint>

// Problem dims
#define B   32
#define S   513
#define T   512      // S-1 context steps
#define D   1024
#define KD  256
#define VD  256
#define H   2048
#define OD  256

// ---------------- scratch (static device globals; no allocation) ----------------
__device__ float g_xK[(size_t)B * T * KD];          // 16 MB
__device__ float g_xV[(size_t)B * T * KD];          // 16 MB
__device__ float g_xQ[B * KD];
__device__ float g_L0[(size_t)B * T * H];           // 128 MB  L0[b][t][h] = xK[b,t]·W_hi0[b,h]
__device__ float g_G [(size_t)B * T * T];           // 32 MB   G[b][t][s]  = xK[b,t]·xK[b,s]
__device__ float g_q0[B * H];
__device__ float g_qk[B * T];
__device__ int   g_last[B * H];
__device__ float g_p  [B * H];                      // p_orig (0 where won)
__device__ float g_w  [B * T];
__device__ float g_t2v[B * VD];
__device__ float g_t2d[B * D];
__device__ float g_mhn[B * VD];

// ---------------- fp32 NT GEMM: C[M,N] = A[M,K] * B[N,K]^T, batched over z -----
__global__ __launch_bounds__(256, 2)
void gemm_nt128(const float* __restrict__ A, const float* __restrict__ Bm, float* __restrict__ C,
                int M, int N, int K, long lda, long ldb, long ldc,
                long sA, long sB, long sC)
{
    A  += (long)blockIdx.z * sA;
    Bm += (long)blockIdx.z * sB;
    C  += (long)blockIdx.z * sC;

    __shared__ float As[8][132];
    __shared__ float Bs[8][132];

    const int tid  = threadIdx.x;
    const int row0 = blockIdx.y * 128;
    const int col0 = blockIdx.x * 128;
    const int lr   = tid >> 1;          // 0..127
    const int lc   = (tid & 1) * 4;     // 0 or 4
    const int mr   = (tid >> 4) * 8;    // 0..120
    const int nc   = (tid & 15) * 8;    // 0..120

    float acc[8][8];
    #pragma unroll
    for (int i = 0; i < 8; i++)
        #pragma unroll
        for (int j = 0; j < 8; j++) acc[i][j] = 0.f;

    const bool aval = (row0 + lr) < M;
    const bool bval = (col0 + lr) < N;
    const float* Aptr = A  + (long)(row0 + lr) * lda + lc;
    const float* Bptr = Bm + (long)(col0 + lr) * ldb + lc;

    for (int k0 = 0; k0 < K; k0 += 8) {
        float4 a4 = make_float4(0.f, 0.f, 0.f, 0.f);
        float4 b4 = make_float4(0.f, 0.f, 0.f, 0.f);
        if (aval) a4 = *(const float4*)(Aptr + k0);
        if (bval) b4 = *(const float4*)(Bptr + k0);
        __syncthreads();
        As[lc + 0][lr] = a4.x; As[lc + 1][lr] = a4.y; As[lc + 2][lr] = a4.z; As[lc + 3][lr] = a4.w;
        Bs[lc + 0][lr] = b4.x; Bs[lc + 1][lr] = b4.y; Bs[lc + 2][lr] = b4.z; Bs[lc + 3][lr] = b4.w;
        __syncthreads();
        #pragma unroll
        for (int k = 0; k < 8; k++) {
            float4 a0 = *(const float4*)(&As[k][mr]);
            float4 a1 = *(const float4*)(&As[k][mr + 4]);
            float4 b0 = *(const float4*)(&Bs[k][nc]);
            float4 b1 = *(const float4*)(&Bs[k][nc + 4]);
            float ra[8] = {a0.x, a0.y, a0.z, a0.w, a1.x, a1.y, a1.z, a1.w};
            float rb[8] = {b0.x, b0.y, b0.z, b0.w, b1.x, b1.y, b1.z, b1.w};
            #pragma unroll
            for (int i = 0; i < 8; i++)
                #pragma unroll
                for (int j = 0; j < 8; j++)
                    acc[i][j] += ra[i] * rb[j];
        }
    }

    #pragma unroll
    for (int i = 0; i < 8; i++) {
        int r = row0 + mr + i;
        if (r < M) {
            float* crow = C + (long)r * ldc + col0 + nc;
            #pragma unroll
            for (int j = 0; j < 8; j++)
                if (col0 + nc + j < N) crow[j] = acc[i][j];
        }
    }
}

// ---------------- warp-per-row dot:  out[b*rows+r] = A[b*rows+r,:256] . xQ[b] --
__global__ void rowdot_kernel(const float* __restrict__ A, const float* __restrict__ xQ,
                              float* __restrict__ out, int rowsPerBatch)
{
    long gw = ((long)blockIdx.x * blockDim.x + threadIdx.x) >> 5;
    int lane = threadIdx.x & 31;
    long total = (long)B * rowsPerBatch;
    if (gw >= total) return;
    int b = (int)(gw / rowsPerBatch);
    const float* a = A + gw * KD;
    const float* q = xQ + b * KD;
    float acc = 0.f;
    #pragma unroll
    for (int i = 0; i < 8; i++) acc += a[lane + i * 32] * q[lane + i * 32];
    #pragma unroll
    for (int off = 16; off; off >>= 1) acc += __shfl_xor_sync(0xffffffffu, acc, off);
    if (lane == 0) out[gw] = acc;
}

// ---------------- serial one-winner scan (one block per batch) ----------------
__device__ __forceinline__ void cp16(void* smem_ptr, const void* gptr)
{
    unsigned s = (unsigned)__cvta_generic_to_shared(smem_ptr);
    asm volatile("cp.async.cg.shared.global [%0], [%1], 16;" :: "r"(s), "l"(gptr));
}

__global__ __launch_bounds__(256, 1)
void scan_kernel(const float* __restrict__ L0, const float* __restrict__ G, int* __restrict__ lastOut)
{
    const int b = blockIdx.x;
    const int tid = threadIdx.x;
    const float* L0b = L0 + (long)b * T * H;
    const float* Gb  = G  + (long)b * T * T;

    __shared__ float l0s[4][H];   // 32 KB ring of L0 rows
    __shared__ float rv[8];
    __shared__ int   ri[8];

    int   lastv[8];
    float gv[8];
    #pragma unroll
    for (int i = 0; i < 8; i++) { lastv[i] = -1; gv[i] = 0.f; }

    // prologue: prefetch rows 0..3
    #pragma unroll
    for (int r = 0; r < 4; r++) {
        const float4* src = (const float4*)(L0b + (long)r * H);
        float4* dst = (float4*)l0s[r & 3];
        cp16(dst + tid, src + tid);
        cp16(dst + tid + 256, src + tid + 256);
        asm volatile("cp.async.commit_group;");
    }

    for (int t = 0; t < T; t++) {
        asm volatile("cp.async.wait_group 3;");
        __syncthreads();                       // row t ready; also fences rv/ri reuse

        const float* rowbuf = l0s[t & 3];
        float bv = -3.4e38f; int bi = 0;
        #pragma unroll
        for (int i = 0; i < 8; i++) {
            int h = i * 256 + tid;
            float v = (lastv[i] < 0) ? rowbuf[h] : gv[i];
            if (v > bv) { bv = v; bi = h; }     // ascending h => first-max tie-break
        }
        #pragma unroll
        for (int off = 16; off; off >>= 1) {
            float ov = __shfl_xor_sync(0xffffffffu, bv, off);
            int   oi = __shfl_xor_sync(0xffffffffu, bi, off);
            if (ov > bv || (ov == bv && oi < bi)) { bv = ov; bi = oi; }
        }
        int wwid = tid >> 5;
        if ((tid & 31) == 0) { rv[wwid] = bv; ri[wwid] = bi; }
        __syncthreads();

        float fv = rv[0]; int fi = ri[0];
        #pragma unroll
        for (int wp = 1; wp < 8; wp++) {
            float ov = rv[wp]; int oi = ri[wp];
            if (ov > fv || (ov == fv && oi < fi)) { fv = ov; fi = oi; }
        }
        // winner fi at step t: update owner's state (thread-local; no other thread reads it)
        if ((fi & 255) == tid) lastv[fi >> 8] = t;

        // prefetch L0 row t+4 into the slot we just finished reading
        if (t + 4 < T) {
            const float4* src = (const float4*)(L0b + (long)(t + 4) * H);
            float4* dst = (float4*)l0s[t & 3];
            cp16(dst + tid, src + tid);
            cp16(dst + tid + 256, src + tid + 256);
        }
        asm volatile("cp.async.commit_group;");  // always commit to keep group count aligned

        // prefetch G values for step t+1 (winner slot picks up G[t+1][t] naturally)
        if (t + 1 < T) {
            const float* Grow = Gb + (long)(t + 1) * T;
            #pragma unroll
            for (int i = 0; i < 8; i++)
                if (lastv[i] >= 0) gv[i] = Grow[lastv[i]];
        }
    }
    __syncthreads();
    #pragma unroll
    for (int i = 0; i < 8; i++) lastOut[b * H + i * 256 + tid] = lastv[i];
}

// ---------------- softmax over final logits + scatter of won mass -------------
__global__ void softmax_scatter(const int* __restrict__ last, const float* __restrict__ q0,
                                const float* __restrict__ qk, float* __restrict__ p, float* __restrict__ w)
{
    const int b = blockIdx.x, tid = threadIdx.x;
    __shared__ float red[8];
    int ls[8]; float v[8];
    #pragma unroll
    for (int i = 0; i < 8; i++) {
        int h = i * 256 + tid;
        ls[i] = last[b * H + h];
        v[i] = (ls[i] < 0) ? q0[b * H + h] : qk[b * T + ls[i]];
    }
    float mx = v[0];
    #pragma unroll
    for (int i = 1; i < 8; i++) mx = fmaxf(mx, v[i]);
    #pragma unroll
    for (int off = 16; off; off >>= 1) mx = fmaxf(mx, __shfl_xor_sync(0xffffffffu, mx, off));
    int wwid = tid >> 5;
    if ((tid & 31) == 0) red[wwid] = mx;
    __syncthreads();
    float m = red[0];
    #pragma unroll
    for (int k = 1; k < 8; k++) m = fmaxf(m, red[k]);
    __syncthreads();

    float e[8]; float s = 0.f;
    #pragma unroll
    for (int i = 0; i < 8; i++) { e[i] = expf(v[i] - m); s += e[i]; }
    #pragma unroll
    for (int off = 16; off; off >>= 1) s += __shfl_xor_sync(0xffffffffu, s, off);
    if ((tid & 31) == 0) red[wwid] = s;
    __syncthreads();
    float tot = 0.f;
    #pragma unroll
    for (int k = 0; k < 8; k++) tot += red[k];
    float inv = 1.f / tot;

    w[b * T + tid] = 0.f;
    w[b * T + 256 + tid] = 0.f;
    __syncthreads();
    #pragma unroll
    for (int i = 0; i < 8; i++) {
        float pi = e[i] * inv;
        p[b * H + i * 256 + tid] = (ls[i] < 0) ? pi : 0.f;
        if (ls[i] >= 0) w[b * T + ls[i]] = pi;   // injective: one winner per step
    }
}

// ---------------- t2: weighted sums over time of xV and ctx -------------------
__global__ void t2_kernel(const float* __restrict__ xV, const float* __restrict__ x,
                          const float* __restrict__ w, float* __restrict__ t2v, float* __restrict__ t2d)
{
    const int b = blockIdx.x, j = blockIdx.y, tid = threadIdx.x;
    __shared__ float ws[T];
    ws[tid] = w[b * T + tid];
    ws[tid + 256] = w[b * T + 256 + tid];
    __syncthreads();
    float acc = 0.f;
    if (j == 0) {
        const float* base = xV + (long)b * T * VD + tid;
        #pragma unroll 4
        for (int t = 0; t < T; t++) {
            float wt = ws[t];
            if (wt != 0.f) acc += wt * base[(long)t * VD];
        }
        t2v[b * VD + tid] = acc;
    } else {
        int d = (j - 1) * 256 + tid;
        const float* base = x + (long)b * S * D + d;
        #pragma unroll 4
        for (int t = 0; t < T; t++) {
            float wt = ws[t];
            if (wt != 0.f) acc += wt * base[(long)t * D];
        }
        t2d[b * D + d] = acc;
    }
}

// ---------------- mhn_out = W_oh0 @ p_orig + t2v ------------------------------
__global__ void mhn_kernel(const float* __restrict__ W_oh0, const float* __restrict__ p,
                           const float* __restrict__ t2v, float* __restrict__ mhn)
{
    const int b = blockIdx.x, vg = blockIdx.y, tid = threadIdx.x;
    __shared__ float ps[H];
    #pragma unroll
    for (int i = 0; i < 8; i++) ps[i * 256 + tid] = p[b * H + i * 256 + tid];
    __syncthreads();
    const int wwid = tid >> 5, lane = tid & 31;
    const int v = vg * 8 + wwid;
    const float* row = W_oh0 + ((long)b * VD + v) * H;
    float acc = 0.f;
    #pragma unroll 4
    for (int h = lane; h < H; h += 32) acc += row[h] * ps[h];
    #pragma unroll
    for (int off = 16; off; off >>= 1) acc += __shfl_xor_sync(0xffffffffu, acc, off);
    if (lane == 0) mhn[b * VD + v] = acc + t2v[b * VD + v];
}

// ---------------- reinst = W_reinst0^T-weighted + t2d -> d_out[8192..] --------
__global__ void reinst_kernel(const float* __restrict__ W_r0, const float* __restrict__ p,
                              const float* __restrict__ t2d, float* __restrict__ outbuf)
{
    const int b = blockIdx.x, dc = blockIdx.y, tid = threadIdx.x;
    __shared__ float ps[H];
    #pragma unroll
    for (int i = 0; i < 8; i++) ps[i * 256 + tid] = p[b * H + i * 256 + tid];
    __syncthreads();
    const int d = dc * 256 + tid;
    const float* base = W_r0 + (long)b * H * D + d;
    float acc = t2d[b * D + d];
    #pragma unroll 4
    for (int h = 0; h < H; h++) {
        float ph = ps[h];
        if (ph != 0.f) acc += ph * base[(long)h * D];
    }
    outbuf[B * OD + b * D + d] = acc;
}

// ---------------- out = mhn @ W_proj^T; also copy xQ to tail ------------------
__global__ void out_kernel(const float* __restrict__ W_proj, const float* __restrict__ mhn,
                           const float* __restrict__ xQ, float* __restrict__ dout)
{
    const int b = blockIdx.x, tid = threadIdx.x;
    __shared__ float ms[VD];
    ms[tid] = mhn[b * VD + tid];
    __syncthreads();
    const float* row = W_proj + tid * VD;
    float acc = 0.f;
    #pragma unroll 4
    for (int v = 0; v < VD; v++) acc += row[v] * ms[v];
    dout[b * OD + tid] = acc;
    dout[B * OD + B * D + b * KD + tid] = xQ[b * KD + tid];
}

// ---------------- launch ------------------------------------------------------
extern "C" void kernel_launch(void* const* d_in, const int* in_sizes, int n_in,
                              void* d_out, int out_size)
{
    const float* x        = (const float*)d_in[0];
    const float* W_Q      = (const float*)d_in[1];
    const float* W_K      = (const float*)d_in[2];
    const float* W_V      = (const float*)d_in[3];
    const float* W_proj   = (const float*)d_in[4];
    const float* W_hi0    = (const float*)d_in[5];
    const float* W_oh0    = (const float*)d_in[6];
    const float* W_rein0  = (const float*)d_in[7];
    float* out = (float*)d_out;

    float *pxK, *pxV, *pxQ, *pL0, *pG, *pq0, *pqk, *pp, *pw, *pt2v, *pt2d, *pmhn;
    int* plast;
    cudaGetSymbolAddress((void**)&pxK,  g_xK);
    cudaGetSymbolAddress((void**)&pxV,  g_xV);
    cudaGetSymbolAddress((void**)&pxQ,  g_xQ);
    cudaGetSymbolAddress((void**)&pL0,  g_L0);
    cudaGetSymbolAddress((void**)&pG,   g_G);
    cudaGetSymbolAddress((void**)&pq0,  g_q0);
    cudaGetSymbolAddress((void**)&pqk,  g_qk);
    cudaGetSymbolAddress((void**)&plast,g_last);
    cudaGetSymbolAddress((void**)&pp,   g_p);
    cudaGetSymbolAddress((void**)&pw,   g_w);
    cudaGetSymbolAddress((void**)&pt2v, g_t2v);
    cudaGetSymbolAddress((void**)&pt2d, g_t2d);
    cudaGetSymbolAddress((void**)&pmhn, g_mhn);

    dim3 thr(256);

    // projections
    gemm_nt128<<<dim3(2, 4, B), thr>>>(x, W_K, pxK, T, KD, D, D, D, KD, (long)S * D, 0, (long)T * KD);
    gemm_nt128<<<dim3(2, 4, B), thr>>>(x, W_V, pxV, T, KD, D, D, D, KD, (long)S * D, 0, (long)T * KD);
    gemm_nt128<<<dim3(2, 1, 1), thr>>>(x + (long)T * D, W_Q, pxQ, B, KD, D, (long)S * D, D, KD, 0, 0, 0);

    // scan precomputes
    gemm_nt128<<<dim3(4, 4, B), thr>>>(pxK, pxK,   pG,  T, T, KD, KD, KD, T, (long)T * KD, (long)T * KD, (long)T * T);
    gemm_nt128<<<dim3(16, 4, B), thr>>>(pxK, W_hi0, pL0, T, H, KD, KD, KD, H, (long)T * KD, (long)H * KD, (long)T * H);
    rowdot_kernel<<<(B * H) / 8, 256>>>(W_hi0, pxQ, pq0, H);
    rowdot_kernel<<<(B * T) / 8, 256>>>(pxK, pxQ, pqk, T);

    // serial one-winner scan
    scan_kernel<<<B, 256>>>(pL0, pG, plast);

    // epilogue
    softmax_scatter<<<B, 256>>>(plast, pq0, pqk, pp, pw);
    t2_kernel<<<dim3(B, 5), 256>>>(pxV, x, pw, pt2v, pt2d);
    mhn_kernel<<<dim3(B, 32), 256>>>(W_oh0, pp, pt2v, pmhn);
    reinst_kernel<<<dim3(B, 4), 256>>>(W_rein0, pp, pt2d, out);
    out_kernel<<<B, 256>>>(W_proj, pmhn, pxQ, out);
}

// round 7
// speedup vs baseline: 1.2009x; 1.2009x over previous
#include <cuda_runtime.h>
#include <cstdint>

// Problem dims
#define B   32
#define S   513
#define T   512      // S-1 context steps
#define D   1024
#define KD  256
#define VD  256
#define H   2048
#define OD  256

// ---------------- scratch (static device globals; no allocation) ----------------
__device__ float g_xK[(size_t)B * T * KD];          // 16 MB
__device__ float g_xQ[B * KD];
__device__ float g_L0[(size_t)B * T * H];           // 128 MB  L0[b][t][h] = xK[b,t]·W_hi0[b,h]
__device__ float g_G [(size_t)B * T * T];           // 32 MB   G[b][t][s]  = xK[b,t]·xK[b,s]
__device__ float g_q0[B * H];
__device__ float g_qk[B * T];
__device__ int   g_last[B * H];
__device__ float g_p  [B * H];                      // p_orig (0 where won)
__device__ float g_w  [B * T];
__device__ float g_t2v[B * VD];
__device__ float g_t2d[B * D];                      // t2x = sum_t w_t * ctx[t]
__device__ float g_mhn[B * VD];

// ---------------- fp32 NT GEMM: C[M,N] = A[M,K] * B[N,K]^T, batched over z -----
// Double-buffered smem pipeline: one barrier per 8-k tile; LDG issued before the
// FFMA block (covered by ~4096 SMSP-cycles of compute), STS into the spare buffer
// after. triLower=1 skips blocks strictly above the 128x128 block diagonal.
__global__ __launch_bounds__(256, 2)
void gemm_nt128(const float* __restrict__ A, const float* __restrict__ Bm, float* __restrict__ C,
                int M, int N, int K, long lda, long ldb, long ldc,
                long sA, long sB, long sC, int triLower)
{
    if (triLower && blockIdx.x > blockIdx.y) return;

    A  += (long)blockIdx.z * sA;
    Bm += (long)blockIdx.z * sB;
    C  += (long)blockIdx.z * sC;

    __shared__ float As[2][8][132];
    __shared__ float Bs[2][8][132];

    const int tid  = threadIdx.x;
    const int row0 = blockIdx.y * 128;
    const int col0 = blockIdx.x * 128;
    const int lr   = tid >> 1;          // 0..127
    const int lc   = (tid & 1) * 4;     // 0 or 4
    const int mr   = (tid >> 4) * 8;    // 0..120
    const int nc   = (tid & 15) * 8;    // 0..120

    float acc[8][8];
    #pragma unroll
    for (int i = 0; i < 8; i++)
        #pragma unroll
        for (int j = 0; j < 8; j++) acc[i][j] = 0.f;

    const bool aval = (row0 + lr) < M;
    const bool bval = (col0 + lr) < N;
    const float* Aptr = A  + (long)(row0 + lr) * lda + lc;
    const float* Bptr = Bm + (long)(col0 + lr) * ldb + lc;

    float4 a4 = make_float4(0.f, 0.f, 0.f, 0.f);
    float4 b4 = make_float4(0.f, 0.f, 0.f, 0.f);
    if (aval) a4 = *(const float4*)(Aptr);
    if (bval) b4 = *(const float4*)(Bptr);
    As[0][lc + 0][lr] = a4.x; As[0][lc + 1][lr] = a4.y; As[0][lc + 2][lr] = a4.z; As[0][lc + 3][lr] = a4.w;
    Bs[0][lc + 0][lr] = b4.x; Bs[0][lc + 1][lr] = b4.y; Bs[0][lc + 2][lr] = b4.z; Bs[0][lc + 3][lr] = b4.w;

    const int nt = K >> 3;
    for (int it = 0; it < nt; ++it) {
        __syncthreads();                    // buf ready; spare buf free to overwrite
        const int buf = it & 1;

        if (it + 1 < nt) {                  // stage next tile early (hidden by FFMAs)
            int k0 = (it + 1) * 8;
            if (aval) a4 = *(const float4*)(Aptr + k0);
            if (bval) b4 = *(const float4*)(Bptr + k0);
        }

        #pragma unroll
        for (int k = 0; k < 8; k++) {
            float4 a0 = *(const float4*)(&As[buf][k][mr]);
            float4 a1 = *(const float4*)(&As[buf][k][mr + 4]);
            float4 b0 = *(const float4*)(&Bs[buf][k][nc]);
            float4 b1 = *(const float4*)(&Bs[buf][k][nc + 4]);
            float ra[8] = {a0.x, a0.y, a0.z, a0.w, a1.x, a1.y, a1.z, a1.w};
            float rb[8] = {b0.x, b0.y, b0.z, b0.w, b1.x, b1.y, b1.z, b1.w};
            #pragma unroll
            for (int i = 0; i < 8; i++)
                #pragma unroll
                for (int j = 0; j < 8; j++)
                    acc[i][j] += ra[i] * rb[j];
        }

        if (it + 1 < nt) {
            const int nb = buf ^ 1;
            As[nb][lc + 0][lr] = a4.x; As[nb][lc + 1][lr] = a4.y; As[nb][lc + 2][lr] = a4.z; As[nb][lc + 3][lr] = a4.w;
            Bs[nb][lc + 0][lr] = b4.x; Bs[nb][lc + 1][lr] = b4.y; Bs[nb][lc + 2][lr] = b4.z; Bs[nb][lc + 3][lr] = b4.w;
        }
    }

    #pragma unroll
    for (int i = 0; i < 8; i++) {
        int r = row0 + mr + i;
        if (r < M) {
            float* crow = C + (long)r * ldc + col0 + nc;
            #pragma unroll
            for (int j = 0; j < 8; j++)
                if (col0 + nc + j < N) crow[j] = acc[i][j];
        }
    }
}

// ---------------- warp-per-row dot:  out[b*rows+r] = A[b*rows+r,:256] . xQ[b] --
__global__ void rowdot_kernel(const float* __restrict__ A, const float* __restrict__ xQ,
                              float* __restrict__ out, int rowsPerBatch)
{
    long gw = ((long)blockIdx.x * blockDim.x + threadIdx.x) >> 5;
    int lane = threadIdx.x & 31;
    long total = (long)B * rowsPerBatch;
    if (gw >= total) return;
    int b = (int)(gw / rowsPerBatch);
    const float* a = A + gw * KD;
    const float* q = xQ + b * KD;
    float acc = 0.f;
    #pragma unroll
    for (int i = 0; i < 8; i++) acc += a[lane + i * 32] * q[lane + i * 32];
    #pragma unroll
    for (int off = 16; off; off >>= 1) acc += __shfl_xor_sync(0xffffffffu, acc, off);
    if (lane == 0) out[gw] = acc;
}

// ---------------- serial one-winner scan (one block per batch) ----------------
__device__ __forceinline__ void cp16(void* smem_ptr, const void* gptr)
{
    unsigned s = (unsigned)__cvta_generic_to_shared(smem_ptr);
    asm volatile("cp.async.cg.shared.global [%0], [%1], 16;" :: "r"(s), "l"(gptr));
}

__global__ __launch_bounds__(256, 1)
void scan_kernel(const float* __restrict__ L0, const float* __restrict__ G, int* __restrict__ lastOut)
{
    const int b = blockIdx.x;
    const int tid = threadIdx.x;
    const float* L0b = L0 + (long)b * T * H;
    const float* Gb  = G  + (long)b * T * T;

    __shared__ float l0s[4][H];   // 32 KB ring of L0 rows
    __shared__ float rv[8];
    __shared__ int   ri[8];

    int   lastv[8];
    float gv[8];
    #pragma unroll
    for (int i = 0; i < 8; i++) { lastv[i] = -1; gv[i] = 0.f; }

    // prologue: prefetch rows 0..3
    #pragma unroll
    for (int r = 0; r < 4; r++) {
        const float4* src = (const float4*)(L0b + (long)r * H);
        float4* dst = (float4*)l0s[r & 3];
        cp16(dst + tid, src + tid);
        cp16(dst + tid + 256, src + tid + 256);
        asm volatile("cp.async.commit_group;");
    }

    for (int t = 0; t < T; t++) {
        asm volatile("cp.async.wait_group 3;");
        __syncthreads();                       // row t ready; also fences rv/ri reuse

        const float* rowbuf = l0s[t & 3];
        float bv = -3.4e38f; int bi = 0;
        #pragma unroll
        for (int i = 0; i < 8; i++) {
            int h = i * 256 + tid;
            float v = (lastv[i] < 0) ? rowbuf[h] : gv[i];
            if (v > bv) { bv = v; bi = h; }     // ascending h => first-max tie-break
        }
        #pragma unroll
        for (int off = 16; off; off >>= 1) {
            float ov = __shfl_xor_sync(0xffffffffu, bv, off);
            int   oi = __shfl_xor_sync(0xffffffffu, bi, off);
            if (ov > bv || (ov == bv && oi < bi)) { bv = ov; bi = oi; }
        }
        int wwid = tid >> 5;
        if ((tid & 31) == 0) { rv[wwid] = bv; ri[wwid] = bi; }
        __syncthreads();

        float fv = rv[0]; int fi = ri[0];
        #pragma unroll
        for (int wp = 1; wp < 8; wp++) {
            float ov = rv[wp]; int oi = ri[wp];
            if (ov > fv || (ov == fv && oi < fi)) { fv = ov; fi = oi; }
        }
        // winner fi at step t: update owner's state (thread-local; no other thread reads it)
        if ((fi & 255) == tid) lastv[fi >> 8] = t;

        // prefetch L0 row t+4 into the slot we just finished reading
        if (t + 4 < T) {
            const float4* src = (const float4*)(L0b + (long)(t + 4) * H);
            float4* dst = (float4*)l0s[t & 3];
            cp16(dst + tid, src + tid);
            cp16(dst + tid + 256, src + tid + 256);
        }
        asm volatile("cp.async.commit_group;");  // always commit to keep group count aligned

        // prefetch G values for step t+1 (winner slot picks up G[t+1][t] naturally)
        if (t + 1 < T) {
            const float* Grow = Gb + (long)(t + 1) * T;
            #pragma unroll
            for (int i = 0; i < 8; i++)
                if (lastv[i] >= 0) gv[i] = Grow[lastv[i]];
        }
    }
    __syncthreads();
    #pragma unroll
    for (int i = 0; i < 8; i++) lastOut[b * H + i * 256 + tid] = lastv[i];
}

// ---------------- softmax over final logits + scatter of won mass -------------
__global__ void softmax_scatter(const int* __restrict__ last, const float* __restrict__ q0,
                                const float* __restrict__ qk, float* __restrict__ p, float* __restrict__ w)
{
    const int b = blockIdx.x, tid = threadIdx.x;
    __shared__ float red[8];
    int ls[8]; float v[8];
    #pragma unroll
    for (int i = 0; i < 8; i++) {
        int h = i * 256 + tid;
        ls[i] = last[b * H + h];
        v[i] = (ls[i] < 0) ? q0[b * H + h] : qk[b * T + ls[i]];
    }
    float mx = v[0];
    #pragma unroll
    for (int i = 1; i < 8; i++) mx = fmaxf(mx, v[i]);
    #pragma unroll
    for (int off = 16; off; off >>= 1) mx = fmaxf(mx, __shfl_xor_sync(0xffffffffu, mx, off));
    int wwid = tid >> 5;
    if ((tid & 31) == 0) red[wwid] = mx;
    __syncthreads();
    float m = red[0];
    #pragma unroll
    for (int k = 1; k < 8; k++) m = fmaxf(m, red[k]);
    __syncthreads();

    float e[8]; float s = 0.f;
    #pragma unroll
    for (int i = 0; i < 8; i++) { e[i] = expf(v[i] - m); s += e[i]; }
    #pragma unroll
    for (int off = 16; off; off >>= 1) s += __shfl_xor_sync(0xffffffffu, s, off);
    if ((tid & 31) == 0) red[wwid] = s;
    __syncthreads();
    float tot = 0.f;
    #pragma unroll
    for (int k = 0; k < 8; k++) tot += red[k];
    float inv = 1.f / tot;

    w[b * T + tid] = 0.f;
    w[b * T + 256 + tid] = 0.f;
    __syncthreads();
    #pragma unroll
    for (int i = 0; i < 8; i++) {
        float pi = e[i] * inv;
        p[b * H + i * 256 + tid] = (ls[i] < 0) ? pi : 0.f;
        if (ls[i] >= 0) w[b * T + ls[i]] = pi;   // injective: one winner per step
    }
}

// ---------------- t2x: weighted sum over time of ctx --------------------------
__global__ void t2_kernel(const float* __restrict__ x, const float* __restrict__ w,
                          float* __restrict__ t2d)
{
    const int b = blockIdx.x, j = blockIdx.y, tid = threadIdx.x;
    __shared__ float ws[T];
    ws[tid] = w[b * T + tid];
    ws[tid + 256] = w[b * T + 256 + tid];
    __syncthreads();
    float acc = 0.f;
    int d = j * 256 + tid;
    const float* base = x + (long)b * S * D + d;
    #pragma unroll 4
    for (int t = 0; t < T; t++) {
        float wt = ws[t];
        if (wt != 0.f) acc += wt * base[(long)t * D];
    }
    t2d[b * D + d] = acc;
}

// ---------------- t2v[b,v] = W_V[v,:] . t2x[b,:]  (replaces the xV GEMM) ------
__global__ void t2v_kernel(const float* __restrict__ W_V, const float* __restrict__ t2x,
                           float* __restrict__ t2v)
{
    const int b = blockIdx.x, vg = blockIdx.y, tid = threadIdx.x;
    __shared__ float xs[D];
    #pragma unroll
    for (int i = 0; i < 4; i++) xs[i * 256 + tid] = t2x[b * D + i * 256 + tid];
    __syncthreads();
    const int wwid = tid >> 5, lane = tid & 31;
    const int v = vg * 8 + wwid;
    const float* row = W_V + (long)v * D;
    float acc = 0.f;
    #pragma unroll 4
    for (int d = lane; d < D; d += 32) acc += row[d] * xs[d];
    #pragma unroll
    for (int off = 16; off; off >>= 1) acc += __shfl_xor_sync(0xffffffffu, acc, off);
    if (lane == 0) t2v[b * VD + v] = acc;
}

// ---------------- mhn_out = W_oh0 @ p_orig + t2v ------------------------------
__global__ void mhn_kernel(const float* __restrict__ W_oh0, const float* __restrict__ p,
                           const float* __restrict__ t2v, float* __restrict__ mhn)
{
    const int b = blockIdx.x, vg = blockIdx.y, tid = threadIdx.x;
    __shared__ float ps[H];
    #pragma unroll
    for (int i = 0; i < 8; i++) ps[i * 256 + tid] = p[b * H + i * 256 + tid];
    __syncthreads();
    const int wwid = tid >> 5, lane = tid & 31;
    const int v = vg * 8 + wwid;
    const float* row = W_oh0 + ((long)b * VD + v) * H;
    float acc = 0.f;
    #pragma unroll 4
    for (int h = lane; h < H; h += 32) acc += row[h] * ps[h];
    #pragma unroll
    for (int off = 16; off; off >>= 1) acc += __shfl_xor_sync(0xffffffffu, acc, off);
    if (lane == 0) mhn[b * VD + v] = acc + t2v[b * VD + v];
}

// ---------------- reinst = W_reinst0^T-weighted + t2d -> d_out[8192..] --------
__global__ void reinst_kernel(const float* __restrict__ W_r0, const float* __restrict__ p,
                              const float* __restrict__ t2d, float* __restrict__ outbuf)
{
    const int b = blockIdx.x, dc = blockIdx.y, tid = threadIdx.x;
    __shared__ float ps[H];
    #pragma unroll
    for (int i = 0; i < 8; i++) ps[i * 256 + tid] = p[b * H + i * 256 + tid];
    __syncthreads();
    const int d = dc * 256 + tid;
    const float* base = W_r0 + (long)b * H * D + d;
    float acc = t2d[b * D + d];
    #pragma unroll 4
    for (int h = 0; h < H; h++) {
        float ph = ps[h];
        if (ph != 0.f) acc += ph * base[(long)h * D];
    }
    outbuf[B * OD + b * D + d] = acc;
}

// ---------------- out = mhn @ W_proj^T; also copy xQ to tail ------------------
__global__ void out_kernel(const float* __restrict__ W_proj, const float* __restrict__ mhn,
                           const float* __restrict__ xQ, float* __restrict__ dout)
{
    const int b = blockIdx.x, tid = threadIdx.x;
    __shared__ float ms[VD];
    ms[tid] = mhn[b * VD + tid];
    __syncthreads();
    const float* row = W_proj + tid * VD;
    float acc = 0.f;
    #pragma unroll 4
    for (int v = 0; v < VD; v++) acc += row[v] * ms[v];
    dout[b * OD + tid] = acc;
    dout[B * OD + B * D + b * KD + tid] = xQ[b * KD + tid];
}

// ---------------- launch ------------------------------------------------------
extern "C" void kernel_launch(void* const* d_in, const int* in_sizes, int n_in,
                              void* d_out, int out_size)
{
    const float* x        = (const float*)d_in[0];
    const float* W_Q      = (const float*)d_in[1];
    const float* W_K      = (const float*)d_in[2];
    const float* W_V      = (const float*)d_in[3];
    const float* W_proj   = (const float*)d_in[4];
    const float* W_hi0    = (const float*)d_in[5];
    const float* W_oh0    = (const float*)d_in[6];
    const float* W_rein0  = (const float*)d_in[7];
    float* out = (float*)d_out;

    float *pxK, *pxQ, *pL0, *pG, *pq0, *pqk, *pp, *pw, *pt2v, *pt2d, *pmhn;
    int* plast;
    cudaGetSymbolAddress((void**)&pxK,  g_xK);
    cudaGetSymbolAddress((void**)&pxQ,  g_xQ);
    cudaGetSymbolAddress((void**)&pL0,  g_L0);
    cudaGetSymbolAddress((void**)&pG,   g_G);
    cudaGetSymbolAddress((void**)&pq0,  g_q0);
    cudaGetSymbolAddress((void**)&pqk,  g_qk);
    cudaGetSymbolAddress((void**)&plast,g_last);
    cudaGetSymbolAddress((void**)&pp,   g_p);
    cudaGetSymbolAddress((void**)&pw,   g_w);
    cudaGetSymbolAddress((void**)&pt2v, g_t2v);
    cudaGetSymbolAddress((void**)&pt2d, g_t2d);
    cudaGetSymbolAddress((void**)&pmhn, g_mhn);

    dim3 thr(256);

    // projections (xV GEMM eliminated: t2v computed from t2x after the scan)
    gemm_nt128<<<dim3(2, 4, B), thr>>>(x, W_K, pxK, T, KD, D, D, D, KD, (long)S * D, 0, (long)T * KD, 0);
    gemm_nt128<<<dim3(2, 1, 1), thr>>>(x + (long)T * D, W_Q, pxQ, B, KD, D, (long)S * D, D, KD, 0, 0, 0, 0);

    // scan precomputes (G: lower-triangle blocks only)
    gemm_nt128<<<dim3(4, 4, B), thr>>>(pxK, pxK,   pG,  T, T, KD, KD, KD, T, (long)T * KD, (long)T * KD, (long)T * T, 1);
    gemm_nt128<<<dim3(16, 4, B), thr>>>(pxK, W_hi0, pL0, T, H, KD, KD, KD, H, (long)T * KD, (long)H * KD, (long)T * H, 0);
    rowdot_kernel<<<(B * H) / 8, 256>>>(W_hi0, pxQ, pq0, H);
    rowdot_kernel<<<(B * T) / 8, 256>>>(pxK, pxQ, pqk, T);

    // serial one-winner scan
    scan_kernel<<<B, 256>>>(pL0, pG, plast);

    // epilogue
    softmax_scatter<<<B, 256>>>(plast, pq0, pqk, pp, pw);
    t2_kernel<<<dim3(B, 4), 256>>>(x, pw, pt2d);
    t2v_kernel<<<dim3(B, 32), 256>>>(W_V, pt2d, pt2v);
    mhn_kernel<<<dim3(B, 32), 256>>>(W_oh0, pp, pt2v, pmhn);
    reinst_kernel<<<dim3(B, 4), 256>>>(W_rein0, pp, pt2d, out);
    out_kernel<<<B, 256>>>(W_proj, pmhn, pxQ, out);
}